// round 3
// baseline (speedup 1.0000x reference)
#include <cuda_runtime.h>
#include <cuda_bf16.h>
#include <math.h>

// Problem constants
#define BATCH 32
#define C_IN  64
#define T_LEN 256
#define ZDIM  32
#define HID0  256
#define HID1  256
#define COUT2 96          // 3*Z
#define MU_ELEMS (BATCH*ZDIM*T_LEN)            // 262144

// Scratch (no allocations allowed -> __device__ globals)
__device__ float g_h0[BATCH * HID0 * T_LEN];       // 8 MB
__device__ float g_h1[BATCH * HID1 * T_LEN];       // 8 MB
__device__ float g_stats[BATCH * COUT2 * T_LEN];   // 3 MB

// ---------------------------------------------------------------------------
// Conv1d (K=3, SAME) as tiled GEMM:  Y[b,o,t] = bias[o] + sum_{i,k} W[o,i,k]*X[b,i,t+k-1]
// Block tile: 64 outputs (o) x 128 positions (t).  256 threads, 4x8 micro-tile.
// ---------------------------------------------------------------------------
template<int CIN, bool RELU>
__global__ __launch_bounds__(256)
void conv_kernel(const float* __restrict__ X, const float* __restrict__ W,
                 const float* __restrict__ Bias, float* __restrict__ Y, int COUT)
{
    constexpr int TILE_T = 128;
    constexpr int TILE_O = 64;
    __shared__ float Xs[16][132];        // cols 0..129 used; stride 132 floats (16B aligned)
    __shared__ float Ws[16][3][TILE_O];

    const int tid = threadIdx.x;
    const int tx  = tid & 15;            // t direction (8 contiguous t's each)
    const int ty  = tid >> 4;            // o direction (4 o's, stride 16)
    const int bt  = blockIdx.x * TILE_T;
    const int bo  = blockIdx.y * TILE_O;
    const int b   = blockIdx.z;

    float acc[4][8];
#pragma unroll
    for (int i = 0; i < 4; ++i)
#pragma unroll
        for (int j = 0; j < 8; ++j) acc[i][j] = 0.f;

    const float* Xb = X + (size_t)b * CIN * T_LEN;

    for (int ci = 0; ci < CIN; ci += 16) {
        // load X tile: rows ci..ci+15, t = bt-1 .. bt+128  (130 cols, zero-padded SAME)
        for (int idx = tid; idx < 16 * 130; idx += 256) {
            int row = idx / 130, col = idx % 130;
            int t = bt + col - 1;
            float v = 0.f;
            if (t >= 0 && t < T_LEN) v = Xb[(ci + row) * T_LEN + t];
            Xs[row][col] = v;
        }
        // load W tile: Ws[i][k][o]
        for (int idx = tid; idx < 16 * 3 * TILE_O; idx += 256) {
            int i = idx / (3 * TILE_O);
            int rem = idx % (3 * TILE_O);
            int k = rem / TILE_O, o = rem % TILE_O;
            int og = bo + o;
            float v = 0.f;
            if (og < COUT) v = W[((size_t)og * CIN + ci + i) * 3 + k];
            Ws[i][k][o] = v;
        }
        __syncthreads();

#pragma unroll
        for (int il = 0; il < 16; ++il) {
            float xr[10];
#pragma unroll
            for (int u = 0; u < 10; ++u) xr[u] = Xs[il][8 * tx + u];
#pragma unroll
            for (int oo = 0; oo < 4; ++oo) {
#pragma unroll
                for (int k = 0; k < 3; ++k) {
                    float w = Ws[il][k][ty + 16 * oo];
#pragma unroll
                    for (int tt = 0; tt < 8; ++tt)
                        acc[oo][tt] = fmaf(w, xr[tt + k], acc[oo][tt]);
                }
            }
        }
        __syncthreads();
    }

    // epilogue: bias (+ relu), coalesced stores
#pragma unroll
    for (int oo = 0; oo < 4; ++oo) {
        int o = bo + ty + 16 * oo;
        if (o >= COUT) continue;
        float bv = Bias[o];
        float* yp = Y + ((size_t)b * COUT + o) * T_LEN + bt + 8 * tx;
#pragma unroll
        for (int tt = 0; tt < 8; ++tt) {
            float v = acc[oo][tt] + bv;
            if (RELU) v = fmaxf(v, 0.f);
            yp[tt] = v;
        }
    }
}

// ---------------------------------------------------------------------------
// mu copy: d_out[0 : B*Z*T) = stats[:, :Z, :]
// ---------------------------------------------------------------------------
__global__ __launch_bounds__(256)
void mu_kernel(const float* __restrict__ stats, float* __restrict__ out)
{
    int id = blockIdx.x * 256 + threadIdx.x;                  // [0, 262144)
    int b  = id >> 13;                                        // / (32*256)
    int r  = id & 8191;                                       // c*256 + t
    out[id] = stats[(size_t)b * (COUT2 * T_LEN) + r];
}

__device__ __forceinline__ float softplus_f(float x)
{
    // logaddexp(x, 0) = max(x,0) + log1p(exp(-|x|))
    return fmaxf(x, 0.f) + log1pf(expf(-fabsf(x)));
}

// ---------------------------------------------------------------------------
// Triangular fill.  P is upper-bidiagonal with diag d_i = softplus(.)+1 and
// superdiag s_i = softplus(.).  cov_u = P^{-1}:
//   cov_u[c][r] = (1/d_r) * prod_{k=c}^{r-1} (-s_k/d_k)      (c <= r)
// scale_tril[r][c] = cov_u[c][r].   Thread = column c; loop over rows r.
// Each iteration: 256 threads store 1024 contiguous bytes (coalesced).
// ---------------------------------------------------------------------------
__global__ __launch_bounds__(256)
void tri_kernel(const float* __restrict__ stats, float* __restrict__ out)
{
    __shared__ float invd[256];
    __shared__ float g[256];

    const int bz = blockIdx.x;            // b*32 + z
    const int b  = bz >> 5;
    const int z  = bz & 31;
    const int c  = threadIdx.x;

    // stats channel layout: [0..31]=mu, even 32+2z -> diag row z, odd 32+2z+1 -> sup row z
    const float* sd = stats + ((size_t)b * COUT2 + 32 + 2 * z) * T_LEN;
    const float* ss = sd + T_LEN;

    float d = softplus_f(sd[c]) + 1.f;
    invd[c] = 1.f / d;
    float s = (c < 255) ? softplus_f(ss[c]) : 0.f;
    g[c] = -s / d;
    __syncthreads();

    float* op = out + MU_ELEMS + ((size_t)bz << 16) + c;
    float p = 1.f;
#pragma unroll 4
    for (int r = 0; r < 256; ++r) {
        float v = 0.f;
        if (r >= c) {
            v = p * invd[r];
            if (!isfinite(v)) v = 0.f;
            p *= g[r];
        }
        op[(size_t)r << 8] = v;
    }
}

// ---------------------------------------------------------------------------
extern "C" void kernel_launch(void* const* d_in, const int* in_sizes, int n_in,
                              void* d_out, int out_size)
{
    const float* x  = (const float*)d_in[0];
    const float* W0 = (const float*)d_in[1];
    const float* b0 = (const float*)d_in[2];
    const float* W1 = (const float*)d_in[3];
    const float* b1 = (const float*)d_in[4];
    const float* W2 = (const float*)d_in[5];
    const float* b2 = (const float*)d_in[6];
    float* out = (float*)d_out;

    float *h0, *h1, *st;
    cudaGetSymbolAddress((void**)&h0, g_h0);
    cudaGetSymbolAddress((void**)&h1, g_h1);
    cudaGetSymbolAddress((void**)&st, g_stats);

    // conv0: CIN=64  -> 256 ch, relu
    conv_kernel<C_IN, true><<<dim3(2, 4, BATCH), 256>>>(x,  W0, b0, h0, HID0);
    // conv1: CIN=256 -> 256 ch, relu
    conv_kernel<HID0, true><<<dim3(2, 4, BATCH), 256>>>(h0, W1, b1, h1, HID1);
    // conv2: CIN=256 -> 96 ch, linear
    conv_kernel<HID1, false><<<dim3(2, 2, BATCH), 256>>>(h1, W2, b2, st, COUT2);

    // mu -> first 262144 outputs
    mu_kernel<<<MU_ELEMS / 256, 256>>>(st, out);
    // scale_tril -> remaining 67.1M outputs
    tri_kernel<<<BATCH * ZDIM, 256>>>(st, out);
}

// round 4
// speedup vs baseline: 1.6395x; 1.6395x over previous
#include <cuda_runtime.h>
#include <cuda_bf16.h>
#include <math.h>

// Problem constants
#define BATCH 32
#define C_IN  64
#define T_LEN 256
#define ZDIM  32
#define HID0  256
#define HID1  256
#define COUT2 96          // 3*Z
#define MU_ELEMS (BATCH*ZDIM*T_LEN)            // 262144

typedef unsigned long long u64;

// Scratch (no allocations allowed -> __device__ globals)
__device__ float g_h0[BATCH * HID0 * T_LEN];       // 8 MB
__device__ float g_h1[BATCH * HID1 * T_LEN];       // 8 MB
__device__ float g_stats[BATCH * COUT2 * T_LEN];   // 3 MB
__device__ float g_wt0[192 * 256];                 // W0 transposed [i*3+k][o]
__device__ float g_wt1[768 * 256];                 // W1 transposed
__device__ float g_wt2[768 * 128];                 // W2 transposed, o padded 96->128

// ---------------------------------------------------------------------------
// packed-f32x2 helpers (FFMA2: only reachable via PTX fma.rn.f32x2)
// ---------------------------------------------------------------------------
__device__ __forceinline__ u64 splat2(float x) {
    u64 r; asm("mov.b64 %0,{%1,%1};" : "=l"(r) : "f"(x)); return r;
}
__device__ __forceinline__ void fma2(u64& d, u64 a, u64 b) {
    asm("fma.rn.f32x2 %0,%1,%2,%0;" : "+l"(d) : "l"(a), "l"(b));
}
__device__ __forceinline__ float2 unpk(u64 v) {
    float2 f; asm("mov.b64 {%0,%1},%2;" : "=f"(f.x), "=f"(f.y) : "l"(v)); return f;
}

// ---------------------------------------------------------------------------
// Weight transpose pre-kernel: W[o][i][k] -> Wt[(i*3+k)][o]  (o padded for W2)
// ---------------------------------------------------------------------------
__global__ __launch_bounds__(256)
void transpose_w_kernel(const float* __restrict__ W0, const float* __restrict__ W1,
                        const float* __restrict__ W2)
{
    int e = blockIdx.x * 256 + threadIdx.x;
    const int N0 = 192 * 256, N1 = 768 * 256, N2 = 768 * 128;
    if (e < N0) {
        int r = e >> 8, o = e & 255;
        int i = r / 3, k = r - 3 * i;
        g_wt0[e] = W0[(o * 64 + i) * 3 + k];
    } else if (e < N0 + N1) {
        int e1 = e - N0;
        int r = e1 >> 8, o = e1 & 255;
        int i = r / 3, k = r - 3 * i;
        g_wt1[e1] = W1[(o * 256 + i) * 3 + k];
    } else if (e < N0 + N1 + N2) {
        int e2 = e - N0 - N1;
        int r = e2 >> 7, o = e2 & 127;
        int i = r / 3, k = r - 3 * i;
        g_wt2[e2] = (o < 96) ? W2[(o * 256 + i) * 3 + k] : 0.f;
    }
}

// ---------------------------------------------------------------------------
// Conv1d (K=3, SAME) tiled GEMM with packed-f32x2 math.
// Block tile: 64 outputs (o) x 128 positions (t).  256 threads.
// Thread micro-tile: 4 o (contiguous, as 2 packed pairs) x 8 t.
// Weights come from pre-transposed Wt[(i*3+k)][o] -> packed pairs load free.
// ---------------------------------------------------------------------------
template<int CIN, bool RELU>
__global__ __launch_bounds__(256)
void conv_kernel(const float* __restrict__ X, const float* __restrict__ Wt,
                 const float* __restrict__ Bias, float* __restrict__ Y,
                 int COUT, int WSTRIDE)
{
    __shared__ float Xs[16][132];   // col c <-> t = bt + c - 1, cols 0..129 used
    __shared__ float Ws[48][64];    // [i*3+k][o_local]

    const int tid = threadIdx.x;
    const int tx  = tid & 15;       // t dim: 8 consecutive t's
    const int ty  = tid >> 4;       // o dim: 4 consecutive o's
    const int bt  = blockIdx.x * 128;
    const int bo  = blockIdx.y * 64;
    const int b   = blockIdx.z;

    u64 acc[2][8];
#pragma unroll
    for (int p = 0; p < 2; ++p)
#pragma unroll
        for (int t = 0; t < 8; ++t) acc[p][t] = 0ull;

    const float* Xb = X + (size_t)b * CIN * T_LEN;

#pragma unroll 1
    for (int ci = 0; ci < CIN; ci += 16) {
        // X main tile: 16 rows x 128 cols (t = bt..bt+127) -> Xs cols 1..128
#pragma unroll
        for (int q = 0; q < 2; ++q) {
            int idx = tid + q * 256;          // 0..511
            int row = idx >> 5;               // 0..15
            int c4  = idx & 31;               // 0..31
            float4 v = *(const float4*)(Xb + (ci + row) * T_LEN + bt + c4 * 4);
            Xs[row][1 + 4 * c4 + 0] = v.x;
            Xs[row][1 + 4 * c4 + 1] = v.y;
            Xs[row][1 + 4 * c4 + 2] = v.z;
            Xs[row][1 + 4 * c4 + 3] = v.w;
        }
        // halo columns 0 and 129
        if (tid < 32) {
            int row  = tid & 15;
            int side = tid >> 4;
            if (side == 0) {
                int t = bt - 1;
                Xs[row][0]   = (t >= 0)    ? Xb[(ci + row) * T_LEN + t] : 0.f;
            } else {
                int t = bt + 128;
                Xs[row][129] = (t < T_LEN) ? Xb[(ci + row) * T_LEN + t] : 0.f;
            }
        }
        // W tile: rows 3*ci .. 3*ci+47, cols bo..bo+63  (768 float4 / 256 thr = 3)
#pragma unroll
        for (int q = 0; q < 3; ++q) {
            int idx = tid + q * 256;          // 0..767
            int row = idx >> 4;               // 0..47
            int c4  = idx & 15;               // 0..15
            float4 v = *(const float4*)(Wt + (size_t)(3 * ci + row) * WSTRIDE + bo + 4 * c4);
            *(float4*)&Ws[row][4 * c4] = v;
        }
        __syncthreads();

#pragma unroll
        for (int il = 0; il < 16; ++il) {
            float4 a0 = *(const float4*)&Xs[il][8 * tx];
            float4 a1 = *(const float4*)&Xs[il][8 * tx + 4];
            float2 a2 = *(const float2*)&Xs[il][8 * tx + 8];
            u64 xs[10];
            xs[0] = splat2(a0.x); xs[1] = splat2(a0.y);
            xs[2] = splat2(a0.z); xs[3] = splat2(a0.w);
            xs[4] = splat2(a1.x); xs[5] = splat2(a1.y);
            xs[6] = splat2(a1.z); xs[7] = splat2(a1.w);
            xs[8] = splat2(a2.x); xs[9] = splat2(a2.y);
#pragma unroll
            for (int k = 0; k < 3; ++k) {
                ulonglong2 w = *(const ulonglong2*)&Ws[il * 3 + k][4 * ty];
#pragma unroll
                for (int tt = 0; tt < 8; ++tt) {
                    fma2(acc[0][tt], w.x, xs[tt + k]);
                    fma2(acc[1][tt], w.y, xs[tt + k]);
                }
            }
        }
        __syncthreads();
    }

    // epilogue: unpack pairs, bias (+relu), 2x float4 store per o-row
#pragma unroll
    for (int p = 0; p < 2; ++p) {
        int o0 = bo + 4 * ty + 2 * p;          // lo lane o
        float blo = (o0     < COUT) ? Bias[o0]     : 0.f;
        float bhi = (o0 + 1 < COUT) ? Bias[o0 + 1] : 0.f;
        float lo[8], hi[8];
#pragma unroll
        for (int tt = 0; tt < 8; ++tt) {
            float2 f = unpk(acc[p][tt]);
            lo[tt] = f.x + blo;
            hi[tt] = f.y + bhi;
            if (RELU) { lo[tt] = fmaxf(lo[tt], 0.f); hi[tt] = fmaxf(hi[tt], 0.f); }
        }
        if (o0 < COUT) {
            float* yp = Y + ((size_t)b * COUT + o0) * T_LEN + bt + 8 * tx;
            *(float4*)yp       = make_float4(lo[0], lo[1], lo[2], lo[3]);
            *(float4*)(yp + 4) = make_float4(lo[4], lo[5], lo[6], lo[7]);
        }
        if (o0 + 1 < COUT) {
            float* yp = Y + ((size_t)b * COUT + o0 + 1) * T_LEN + bt + 8 * tx;
            *(float4*)yp       = make_float4(hi[0], hi[1], hi[2], hi[3]);
            *(float4*)(yp + 4) = make_float4(hi[4], hi[5], hi[6], hi[7]);
        }
    }
}

// ---------------------------------------------------------------------------
// mu copy, float4-wide
// ---------------------------------------------------------------------------
__global__ __launch_bounds__(256)
void mu_kernel(const float* __restrict__ stats, float* __restrict__ out)
{
    int id4 = blockIdx.x * 256 + threadIdx.x;     // [0, 65536)
    int b   = id4 >> 11;
    int r4  = id4 & 2047;
    const float4* s4 = (const float4*)stats;
    ((float4*)out)[id4] = s4[b * 6144 + r4];      // 6144 = 96*256/4
}

__device__ __forceinline__ float softplus_f(float x)
{
    return fmaxf(x, 0.f) + log1pf(expf(-fabsf(x)));
}

// ---------------------------------------------------------------------------
// Triangular fill.  cov_u[c][r] = (1/d_r) * prod_{k=c}^{r-1} (-s_k/d_k),
// scale_tril[r][c] = cov_u[c][r].  Thread = 4 consecutive columns (float4 STG).
// Block handles 4 (b,z) pairs with 64 threads each.
// ---------------------------------------------------------------------------
__global__ __launch_bounds__(256)
void tri_kernel(const float* __restrict__ stats, float* __restrict__ out)
{
    __shared__ float invd[4][256];
    __shared__ float gs[4][256];

    const int tid  = threadIdx.x;
    const int sub  = tid >> 6;          // which bz within block
    const int lane = tid & 63;
    const int bz   = blockIdx.x * 4 + sub;
    const int b    = bz >> 5;
    const int z    = bz & 31;
    const int c0   = lane * 4;

    const float* sd = stats + ((size_t)b * COUT2 + 32 + 2 * z) * T_LEN;
    const float* ss = sd + T_LEN;

    float4 dv = *(const float4*)(sd + c0);
    float4 sv = *(const float4*)(ss + c0);
    float d0 = softplus_f(dv.x) + 1.f, d1 = softplus_f(dv.y) + 1.f;
    float d2 = softplus_f(dv.z) + 1.f, d3 = softplus_f(dv.w) + 1.f;
    float s0 = (c0 + 0 < 255) ? softplus_f(sv.x) : 0.f;
    float s1 = (c0 + 1 < 255) ? softplus_f(sv.y) : 0.f;
    float s2 = (c0 + 2 < 255) ? softplus_f(sv.z) : 0.f;
    float s3 = (c0 + 3 < 255) ? softplus_f(sv.w) : 0.f;
    invd[sub][c0 + 0] = 1.f / d0;  gs[sub][c0 + 0] = -s0 / d0;
    invd[sub][c0 + 1] = 1.f / d1;  gs[sub][c0 + 1] = -s1 / d1;
    invd[sub][c0 + 2] = 1.f / d2;  gs[sub][c0 + 2] = -s2 / d2;
    invd[sub][c0 + 3] = 1.f / d3;  gs[sub][c0 + 3] = -s3 / d3;
    __syncthreads();

    float p0 = 1.f, p1 = 1.f, p2 = 1.f, p3 = 1.f;
    float* op = out + MU_ELEMS + ((size_t)bz << 16) + c0;

#pragma unroll 4
    for (int r = 0; r < 256; ++r) {
        float iv = invd[sub][r];
        float gv = gs[sub][r];
        float4 v = make_float4(0.f, 0.f, 0.f, 0.f);
        if (r >= c0)     { v.x = p0 * iv; if (!isfinite(v.x)) v.x = 0.f; p0 *= gv; }
        if (r >= c0 + 1) { v.y = p1 * iv; if (!isfinite(v.y)) v.y = 0.f; p1 *= gv; }
        if (r >= c0 + 2) { v.z = p2 * iv; if (!isfinite(v.z)) v.z = 0.f; p2 *= gv; }
        if (r >= c0 + 3) { v.w = p3 * iv; if (!isfinite(v.w)) v.w = 0.f; p3 *= gv; }
        *(float4*)&op[(size_t)r << 8] = v;
    }
}

// ---------------------------------------------------------------------------
extern "C" void kernel_launch(void* const* d_in, const int* in_sizes, int n_in,
                              void* d_out, int out_size)
{
    const float* x  = (const float*)d_in[0];
    const float* W0 = (const float*)d_in[1];
    const float* b0 = (const float*)d_in[2];
    const float* W1 = (const float*)d_in[3];
    const float* b1 = (const float*)d_in[4];
    const float* W2 = (const float*)d_in[5];
    const float* b2 = (const float*)d_in[6];
    float* out = (float*)d_out;

    float *h0, *h1, *st, *wt0, *wt1, *wt2;
    cudaGetSymbolAddress((void**)&h0,  g_h0);
    cudaGetSymbolAddress((void**)&h1,  g_h1);
    cudaGetSymbolAddress((void**)&st,  g_stats);
    cudaGetSymbolAddress((void**)&wt0, g_wt0);
    cudaGetSymbolAddress((void**)&wt1, g_wt1);
    cudaGetSymbolAddress((void**)&wt2, g_wt2);

    // transpose all weights:   (192+768)*256 + 768*128 = 344064 elems
    transpose_w_kernel<<<1344, 256>>>(W0, W1, W2);

    // conv0: CIN=64  -> 256 ch, relu
    conv_kernel<C_IN, true><<<dim3(2, 4, BATCH), 256>>>(x,  wt0, b0, h0, HID0, 256);
    // conv1: CIN=256 -> 256 ch, relu
    conv_kernel<HID0, true><<<dim3(2, 4, BATCH), 256>>>(h0, wt1, b1, h1, HID1, 256);
    // conv2: CIN=256 -> 96 ch, linear (o padded to 128 in Wt2)
    conv_kernel<HID1, false><<<dim3(2, 2, BATCH), 256>>>(h1, wt2, b2, st, COUT2, 128);

    // mu -> first 262144 outputs
    mu_kernel<<<MU_ELEMS / 1024, 256>>>(st, out);
    // scale_tril -> remaining 67.1M outputs
    tri_kernel<<<(BATCH * ZDIM) / 4, 256>>>(st, out);
}

// round 5
// speedup vs baseline: 2.5646x; 1.5643x over previous
#include <cuda_runtime.h>
#include <cuda_bf16.h>
#include <math.h>

// Problem constants
#define BATCH 32
#define C_IN  64
#define T_LEN 256
#define ZDIM  32
#define HID0  256
#define HID1  256
#define COUT2 96          // 3*Z
#define MU_ELEMS (BATCH*ZDIM*T_LEN)            // 262144

typedef unsigned long long u64;

// Scratch (no allocations allowed -> __device__ globals)
__device__ float g_h0[BATCH * HID0 * T_LEN];       // 8 MB
__device__ float g_h1[BATCH * HID1 * T_LEN];       // 8 MB
__device__ float g_stats[BATCH * COUT2 * T_LEN];   // 3 MB
__device__ float g_wt0[192 * 256];                 // W0 transposed [i*3+k][o]
__device__ float g_wt1[768 * 256];                 // W1 transposed
__device__ float g_wt2[768 * 128];                 // W2 transposed, o padded 96->128

// ---------------------------------------------------------------------------
// packed-f32x2 helpers (FFMA2: only reachable via PTX fma.rn.f32x2)
// ---------------------------------------------------------------------------
__device__ __forceinline__ u64 splat2(float x) {
    u64 r; asm("mov.b64 %0,{%1,%1};" : "=l"(r) : "f"(x)); return r;
}
__device__ __forceinline__ void fma2(u64& d, u64 a, u64 b) {
    asm("fma.rn.f32x2 %0,%1,%2,%0;" : "+l"(d) : "l"(a), "l"(b));
}
__device__ __forceinline__ float2 unpk(u64 v) {
    float2 f; asm("mov.b64 {%0,%1},%2;" : "=f"(f.x), "=f"(f.y) : "l"(v)); return f;
}

// ---------------------------------------------------------------------------
// Weight transpose pre-kernel: W[o][i][k] -> Wt[(i*3+k)][o]  (o padded for W2)
// ---------------------------------------------------------------------------
__global__ __launch_bounds__(256)
void transpose_w_kernel(const float* __restrict__ W0, const float* __restrict__ W1,
                        const float* __restrict__ W2)
{
    int e = blockIdx.x * 256 + threadIdx.x;
    const int N0 = 192 * 256, N1 = 768 * 256, N2 = 768 * 128;
    if (e < N0) {
        int r = e >> 8, o = e & 255;
        int i = r / 3, k = r - 3 * i;
        g_wt0[e] = W0[(o * 64 + i) * 3 + k];
    } else if (e < N0 + N1) {
        int e1 = e - N0;
        int r = e1 >> 8, o = e1 & 255;
        int i = r / 3, k = r - 3 * i;
        g_wt1[e1] = W1[(o * 256 + i) * 3 + k];
    } else if (e < N0 + N1 + N2) {
        int e2 = e - N0 - N1;
        int r = e2 >> 7, o = e2 & 127;
        int i = r / 3, k = r - 3 * i;
        g_wt2[e2] = (o < 96) ? W2[(o * 256 + i) * 3 + k] : 0.f;
    }
}

// ---------------------------------------------------------------------------
// Conv1d (K=3, SAME) tiled GEMM with packed-f32x2 math.
// Block tile: 64 outputs (o) x 64 positions (t).  256 threads.
// Thread micro-tile: 4 o (2 packed pairs) x 4 t.
// Small tile -> 512/256 blocks -> fixes grid-starved occupancy (was 12.5%).
// ---------------------------------------------------------------------------
template<int CIN, bool RELU>
__global__ __launch_bounds__(256)
void conv_kernel(const float* __restrict__ X, const float* __restrict__ Wt,
                 const float* __restrict__ Bias, float* __restrict__ Y,
                 int COUT, int WSTRIDE)
{
    __shared__ float Xs[16][72];    // col c <-> t = bt + c - 1, cols 0..65 used
    __shared__ float Ws[48][64];    // [i*3+k][o_local]

    const int tid = threadIdx.x;
    const int tx  = tid & 15;       // t dim: 4 consecutive t's
    const int ty  = tid >> 4;       // o dim: 4 consecutive o's
    const int bt  = blockIdx.x * 64;
    const int bo  = blockIdx.y * 64;
    const int b   = blockIdx.z;

    u64 acc[2][4];
#pragma unroll
    for (int p = 0; p < 2; ++p)
#pragma unroll
        for (int t = 0; t < 4; ++t) acc[p][t] = 0ull;

    const float* Xb = X + (size_t)b * CIN * T_LEN;

#pragma unroll 1
    for (int ci = 0; ci < CIN; ci += 16) {
        // X main tile: 16 rows x 64 cols (t = bt..bt+63) -> Xs cols 1..64
        {
            int row = tid >> 4;               // 0..15
            int c4  = tid & 15;               // 0..15
            float4 v = *(const float4*)(Xb + (ci + row) * T_LEN + bt + c4 * 4);
            Xs[row][1 + 4 * c4 + 0] = v.x;
            Xs[row][1 + 4 * c4 + 1] = v.y;
            Xs[row][1 + 4 * c4 + 2] = v.z;
            Xs[row][1 + 4 * c4 + 3] = v.w;
        }
        // halo columns 0 and 65
        if (tid < 32) {
            int row  = tid & 15;
            int side = tid >> 4;
            if (side == 0) {
                int t = bt - 1;
                Xs[row][0]  = (t >= 0)    ? Xb[(ci + row) * T_LEN + t] : 0.f;
            } else {
                int t = bt + 64;
                Xs[row][65] = (t < T_LEN) ? Xb[(ci + row) * T_LEN + t] : 0.f;
            }
        }
        // W tile: rows 3*ci .. 3*ci+47, cols bo..bo+63  (768 float4 / 256 thr = 3)
#pragma unroll
        for (int q = 0; q < 3; ++q) {
            int idx = tid + q * 256;          // 0..767
            int row = idx >> 4;               // 0..47
            int c4  = idx & 15;               // 0..15
            float4 v = *(const float4*)(Wt + (size_t)(3 * ci + row) * WSTRIDE + bo + 4 * c4);
            *(float4*)&Ws[row][4 * c4] = v;
        }
        __syncthreads();

#pragma unroll
        for (int il = 0; il < 16; ++il) {
            float4 a0 = *(const float4*)&Xs[il][4 * tx];
            float2 a1 = *(const float2*)&Xs[il][4 * tx + 4];
            u64 xs[6];
            xs[0] = splat2(a0.x); xs[1] = splat2(a0.y);
            xs[2] = splat2(a0.z); xs[3] = splat2(a0.w);
            xs[4] = splat2(a1.x); xs[5] = splat2(a1.y);
#pragma unroll
            for (int k = 0; k < 3; ++k) {
                ulonglong2 w = *(const ulonglong2*)&Ws[il * 3 + k][4 * ty];
#pragma unroll
                for (int tt = 0; tt < 4; ++tt) {
                    fma2(acc[0][tt], w.x, xs[tt + k]);
                    fma2(acc[1][tt], w.y, xs[tt + k]);
                }
            }
        }
        __syncthreads();
    }

    // epilogue: unpack pairs, bias (+relu), 1x float4 store per o-row
#pragma unroll
    for (int p = 0; p < 2; ++p) {
        int o0 = bo + 4 * ty + 2 * p;          // lo lane o
        float blo = (o0     < COUT) ? Bias[o0]     : 0.f;
        float bhi = (o0 + 1 < COUT) ? Bias[o0 + 1] : 0.f;
        float lo[4], hi[4];
#pragma unroll
        for (int tt = 0; tt < 4; ++tt) {
            float2 f = unpk(acc[p][tt]);
            lo[tt] = f.x + blo;
            hi[tt] = f.y + bhi;
            if (RELU) { lo[tt] = fmaxf(lo[tt], 0.f); hi[tt] = fmaxf(hi[tt], 0.f); }
        }
        if (o0 < COUT) {
            float* yp = Y + ((size_t)b * COUT + o0) * T_LEN + bt + 4 * tx;
            *(float4*)yp = make_float4(lo[0], lo[1], lo[2], lo[3]);
        }
        if (o0 + 1 < COUT) {
            float* yp = Y + ((size_t)b * COUT + o0 + 1) * T_LEN + bt + 4 * tx;
            *(float4*)yp = make_float4(hi[0], hi[1], hi[2], hi[3]);
        }
    }
}

// ---------------------------------------------------------------------------
// mu copy, float4-wide
// ---------------------------------------------------------------------------
__global__ __launch_bounds__(256)
void mu_kernel(const float* __restrict__ stats, float* __restrict__ out)
{
    int id4 = blockIdx.x * 256 + threadIdx.x;     // [0, 65536)
    int b   = id4 >> 11;
    int r4  = id4 & 2047;
    const float4* s4 = (const float4*)stats;
    ((float4*)out)[id4] = s4[b * 6144 + r4];      // 6144 = 96*256/4
}

__device__ __forceinline__ float softplus_f(float x)
{
    return fmaxf(x, 0.f) + log1pf(expf(-fabsf(x)));
}

// ---------------------------------------------------------------------------
// Triangular fill.  cov_u[c][r] = (1/d_r) * prod_{k=c}^{r-1} (-s_k/d_k),
// scale_tril[r][c] = cov_u[c][r].  Thread = 4 consecutive columns (float4 STG).
// Block handles 4 (b,z) pairs with 64 threads each.
// ---------------------------------------------------------------------------
__global__ __launch_bounds__(256)
void tri_kernel(const float* __restrict__ stats, float* __restrict__ out)
{
    __shared__ float invd[4][256];
    __shared__ float gs[4][256];

    const int tid  = threadIdx.x;
    const int sub  = tid >> 6;          // which bz within block
    const int lane = tid & 63;
    const int bz   = blockIdx.x * 4 + sub;
    const int b    = bz >> 5;
    const int z    = bz & 31;
    const int c0   = lane * 4;

    const float* sd = stats + ((size_t)b * COUT2 + 32 + 2 * z) * T_LEN;
    const float* ss = sd + T_LEN;

    float4 dv = *(const float4*)(sd + c0);
    float4 sv = *(const float4*)(ss + c0);
    float d0 = softplus_f(dv.x) + 1.f, d1 = softplus_f(dv.y) + 1.f;
    float d2 = softplus_f(dv.z) + 1.f, d3 = softplus_f(dv.w) + 1.f;
    float s0 = (c0 + 0 < 255) ? softplus_f(sv.x) : 0.f;
    float s1 = (c0 + 1 < 255) ? softplus_f(sv.y) : 0.f;
    float s2 = (c0 + 2 < 255) ? softplus_f(sv.z) : 0.f;
    float s3 = (c0 + 3 < 255) ? softplus_f(sv.w) : 0.f;
    invd[sub][c0 + 0] = 1.f / d0;  gs[sub][c0 + 0] = -s0 / d0;
    invd[sub][c0 + 1] = 1.f / d1;  gs[sub][c0 + 1] = -s1 / d1;
    invd[sub][c0 + 2] = 1.f / d2;  gs[sub][c0 + 2] = -s2 / d2;
    invd[sub][c0 + 3] = 1.f / d3;  gs[sub][c0 + 3] = -s3 / d3;
    __syncthreads();

    float p0 = 1.f, p1 = 1.f, p2 = 1.f, p3 = 1.f;
    float* op = out + MU_ELEMS + ((size_t)bz << 16) + c0;

#pragma unroll 4
    for (int r = 0; r < 256; ++r) {
        float iv = invd[sub][r];
        float gv = gs[sub][r];
        float4 v = make_float4(0.f, 0.f, 0.f, 0.f);
        if (r >= c0)     { v.x = p0 * iv; if (!isfinite(v.x)) v.x = 0.f; p0 *= gv; }
        if (r >= c0 + 1) { v.y = p1 * iv; if (!isfinite(v.y)) v.y = 0.f; p1 *= gv; }
        if (r >= c0 + 2) { v.z = p2 * iv; if (!isfinite(v.z)) v.z = 0.f; p2 *= gv; }
        if (r >= c0 + 3) { v.w = p3 * iv; if (!isfinite(v.w)) v.w = 0.f; p3 *= gv; }
        *(float4*)&op[(size_t)r << 8] = v;
    }
}

// ---------------------------------------------------------------------------
extern "C" void kernel_launch(void* const* d_in, const int* in_sizes, int n_in,
                              void* d_out, int out_size)
{
    const float* x  = (const float*)d_in[0];
    const float* W0 = (const float*)d_in[1];
    const float* b0 = (const float*)d_in[2];
    const float* W1 = (const float*)d_in[3];
    const float* b1 = (const float*)d_in[4];
    const float* W2 = (const float*)d_in[5];
    const float* b2 = (const float*)d_in[6];
    float* out = (float*)d_out;

    float *h0, *h1, *st, *wt0, *wt1, *wt2;
    cudaGetSymbolAddress((void**)&h0,  g_h0);
    cudaGetSymbolAddress((void**)&h1,  g_h1);
    cudaGetSymbolAddress((void**)&st,  g_stats);
    cudaGetSymbolAddress((void**)&wt0, g_wt0);
    cudaGetSymbolAddress((void**)&wt1, g_wt1);
    cudaGetSymbolAddress((void**)&wt2, g_wt2);

    // transpose all weights:   (192+768)*256 + 768*128 = 344064 elems
    transpose_w_kernel<<<1344, 256>>>(W0, W1, W2);

    // conv0: CIN=64  -> 256 ch, relu   (grid 4x4x32 = 512 blocks)
    conv_kernel<C_IN, true><<<dim3(4, 4, BATCH), 256>>>(x,  wt0, b0, h0, HID0, 256);
    // conv1: CIN=256 -> 256 ch, relu   (grid 512)
    conv_kernel<HID0, true><<<dim3(4, 4, BATCH), 256>>>(h0, wt1, b1, h1, HID1, 256);
    // conv2: CIN=256 -> 96 ch, linear  (o padded to 128 in Wt2, grid 256)
    conv_kernel<HID1, false><<<dim3(4, 2, BATCH), 256>>>(h1, wt2, b2, st, COUT2, 128);

    // mu -> first 262144 outputs
    mu_kernel<<<MU_ELEMS / 1024, 256>>>(st, out);
    // scale_tril -> remaining 67.1M outputs
    tri_kernel<<<(BATCH * ZDIM) / 4, 256>>>(st, out);
}

// round 6
// speedup vs baseline: 2.6945x; 1.0507x over previous
#include <cuda_runtime.h>
#include <cuda_bf16.h>
#include <math.h>

// Problem constants
#define BATCH 32
#define C_IN  64
#define T_LEN 256
#define ZDIM  32
#define HID0  256
#define HID1  256
#define COUT2 96          // 3*Z
#define MU_ELEMS (BATCH*ZDIM*T_LEN)            // 262144

typedef unsigned long long u64;

// Scratch (no allocations allowed -> __device__ globals)
__device__ float g_h0[BATCH * HID0 * T_LEN];       // 8 MB
__device__ float g_h1[BATCH * HID1 * T_LEN];       // 8 MB
__device__ float g_stats[BATCH * COUT2 * T_LEN];   // 3 MB
__device__ float g_wt0[192 * 256];                 // W0 transposed [i*3+k][o]
__device__ float g_wt1[768 * 256];                 // W1 transposed
__device__ float g_wt2[768 * 128];                 // W2 transposed, o padded 96->128

// ---------------------------------------------------------------------------
// packed-f32x2 helpers (FFMA2: only reachable via PTX fma.rn.f32x2)
// ---------------------------------------------------------------------------
__device__ __forceinline__ u64 splat2(float x) {
    u64 r; asm("mov.b64 %0,{%1,%1};" : "=l"(r) : "f"(x)); return r;
}
__device__ __forceinline__ void fma2(u64& d, u64 a, u64 b) {
    asm("fma.rn.f32x2 %0,%1,%2,%0;" : "+l"(d) : "l"(a), "l"(b));
}
__device__ __forceinline__ float2 unpk(u64 v) {
    float2 f; asm("mov.b64 {%0,%1},%2;" : "=f"(f.x), "=f"(f.y) : "l"(v)); return f;
}

// ---------------------------------------------------------------------------
// Weight transpose pre-kernel: W[o][i][k] -> Wt[(i*3+k)][o]  (o padded for W2)
// ---------------------------------------------------------------------------
__global__ __launch_bounds__(256)
void transpose_w_kernel(const float* __restrict__ W0, const float* __restrict__ W1,
                        const float* __restrict__ W2)
{
    int e = blockIdx.x * 256 + threadIdx.x;
    const int N0 = 192 * 256, N1 = 768 * 256, N2 = 768 * 128;
    if (e < N0) {
        int r = e >> 8, o = e & 255;
        int i = r / 3, k = r - 3 * i;
        g_wt0[e] = W0[(o * 64 + i) * 3 + k];
    } else if (e < N0 + N1) {
        int e1 = e - N0;
        int r = e1 >> 8, o = e1 & 255;
        int i = r / 3, k = r - 3 * i;
        g_wt1[e1] = W1[(o * 256 + i) * 3 + k];
    } else if (e < N0 + N1 + N2) {
        int e2 = e - N0 - N1;
        int r = e2 >> 7, o = e2 & 127;
        int i = r / 3, k = r - 3 * i;
        g_wt2[e2] = (o < 96) ? W2[(o * 256 + i) * 3 + k] : 0.f;
    }
}

// ---------------------------------------------------------------------------
// Conv1d (K=3, SAME) tiled GEMM with packed-f32x2 math.
// Block tile: 64 outputs (o) x 32 positions (t).  128 threads.
// Thread micro-tile: 4 o (2 packed pairs) x 4 t.
// 128-thread blocks (8K regs/block) -> up to 8 blocks/SM; grids 1024/512.
// ---------------------------------------------------------------------------
template<int CIN, bool RELU>
__global__ __launch_bounds__(128, 8)
void conv_kernel(const float* __restrict__ X, const float* __restrict__ Wt,
                 const float* __restrict__ Bias, float* __restrict__ Y,
                 int COUT, int WSTRIDE)
{
    __shared__ float Xs[16][40];    // col c <-> t = bt + c - 1, cols 0..33 used
    __shared__ float Ws[48][64];    // [i*3+k][o_local]

    const int tid = threadIdx.x;
    const int tx  = tid & 7;        // t dim: 4 consecutive t's (32 total)
    const int ty  = tid >> 3;       // o dim: 4 consecutive o's (64 total)
    const int bt  = blockIdx.x * 32;
    const int bo  = blockIdx.y * 64;
    const int b   = blockIdx.z;

    u64 acc[2][4];
#pragma unroll
    for (int p = 0; p < 2; ++p)
#pragma unroll
        for (int t = 0; t < 4; ++t) acc[p][t] = 0ull;

    const float* Xb = X + (size_t)b * CIN * T_LEN;

#pragma unroll 1
    for (int ci = 0; ci < CIN; ci += 16) {
        // X main tile: 16 rows x 32 cols (t = bt..bt+31) -> Xs cols 1..32
        {
            int row = tid >> 3;               // 0..15
            int c4  = tid & 7;                // 0..7
            float4 v = *(const float4*)(Xb + (ci + row) * T_LEN + bt + c4 * 4);
            Xs[row][1 + 4 * c4 + 0] = v.x;
            Xs[row][1 + 4 * c4 + 1] = v.y;
            Xs[row][1 + 4 * c4 + 2] = v.z;
            Xs[row][1 + 4 * c4 + 3] = v.w;
        }
        // halo columns 0 and 33
        if (tid < 32) {
            int row  = tid & 15;
            int side = tid >> 4;
            if (side == 0) {
                int t = bt - 1;
                Xs[row][0]  = (t >= 0)    ? Xb[(ci + row) * T_LEN + t] : 0.f;
            } else {
                int t = bt + 32;
                Xs[row][33] = (t < T_LEN) ? Xb[(ci + row) * T_LEN + t] : 0.f;
            }
        }
        // W tile: rows 3*ci .. 3*ci+47, cols bo..bo+63  (768 float4 / 128 thr = 6)
#pragma unroll
        for (int q = 0; q < 6; ++q) {
            int idx = tid + q * 128;          // 0..767
            int row = idx >> 4;               // 0..47
            int c4  = idx & 15;               // 0..15
            float4 v = *(const float4*)(Wt + (size_t)(3 * ci + row) * WSTRIDE + bo + 4 * c4);
            *(float4*)&Ws[row][4 * c4] = v;
        }
        __syncthreads();

#pragma unroll
        for (int il = 0; il < 16; ++il) {
            float4 a0 = *(const float4*)&Xs[il][4 * tx];
            float2 a1 = *(const float2*)&Xs[il][4 * tx + 4];
            u64 xs[6];
            xs[0] = splat2(a0.x); xs[1] = splat2(a0.y);
            xs[2] = splat2(a0.z); xs[3] = splat2(a0.w);
            xs[4] = splat2(a1.x); xs[5] = splat2(a1.y);
#pragma unroll
            for (int k = 0; k < 3; ++k) {
                ulonglong2 w = *(const ulonglong2*)&Ws[il * 3 + k][4 * ty];
#pragma unroll
                for (int tt = 0; tt < 4; ++tt) {
                    fma2(acc[0][tt], w.x, xs[tt + k]);
                    fma2(acc[1][tt], w.y, xs[tt + k]);
                }
            }
        }
        __syncthreads();
    }

    // epilogue: unpack pairs, bias (+relu), 1x float4 store per o-row
#pragma unroll
    for (int p = 0; p < 2; ++p) {
        int o0 = bo + 4 * ty + 2 * p;          // lo lane o
        float blo = (o0     < COUT) ? Bias[o0]     : 0.f;
        float bhi = (o0 + 1 < COUT) ? Bias[o0 + 1] : 0.f;
        float lo[4], hi[4];
#pragma unroll
        for (int tt = 0; tt < 4; ++tt) {
            float2 f = unpk(acc[p][tt]);
            lo[tt] = f.x + blo;
            hi[tt] = f.y + bhi;
            if (RELU) { lo[tt] = fmaxf(lo[tt], 0.f); hi[tt] = fmaxf(hi[tt], 0.f); }
        }
        if (o0 < COUT) {
            float* yp = Y + ((size_t)b * COUT + o0) * T_LEN + bt + 4 * tx;
            *(float4*)yp = make_float4(lo[0], lo[1], lo[2], lo[3]);
        }
        if (o0 + 1 < COUT) {
            float* yp = Y + ((size_t)b * COUT + o0 + 1) * T_LEN + bt + 4 * tx;
            *(float4*)yp = make_float4(hi[0], hi[1], hi[2], hi[3]);
        }
    }
}

// ---------------------------------------------------------------------------
// mu copy, float4-wide
// ---------------------------------------------------------------------------
__global__ __launch_bounds__(256)
void mu_kernel(const float* __restrict__ stats, float* __restrict__ out)
{
    int id4 = blockIdx.x * 256 + threadIdx.x;     // [0, 65536)
    int b   = id4 >> 11;
    int r4  = id4 & 2047;
    const float4* s4 = (const float4*)stats;
    ((float4*)out)[id4] = s4[b * 6144 + r4];      // 6144 = 96*256/4
}

__device__ __forceinline__ float softplus_f(float x)
{
    return fmaxf(x, 0.f) + log1pf(expf(-fabsf(x)));
}

// ---------------------------------------------------------------------------
// Triangular fill.  cov_u[c][r] = (1/d_r) * prod_{k=c}^{r-1} (-s_k/d_k),
// scale_tril[r][c] = cov_u[c][r].  Thread = 4 consecutive columns (float4 STG).
// Block handles 4 (b,z) pairs with 64 threads each.
// ---------------------------------------------------------------------------
__global__ __launch_bounds__(256)
void tri_kernel(const float* __restrict__ stats, float* __restrict__ out)
{
    __shared__ float invd[4][256];
    __shared__ float gs[4][256];

    const int tid  = threadIdx.x;
    const int sub  = tid >> 6;          // which bz within block
    const int lane = tid & 63;
    const int bz   = blockIdx.x * 4 + sub;
    const int b    = bz >> 5;
    const int z    = bz & 31;
    const int c0   = lane * 4;

    const float* sd = stats + ((size_t)b * COUT2 + 32 + 2 * z) * T_LEN;
    const float* ss = sd + T_LEN;

    float4 dv = *(const float4*)(sd + c0);
    float4 sv = *(const float4*)(ss + c0);
    float d0 = softplus_f(dv.x) + 1.f, d1 = softplus_f(dv.y) + 1.f;
    float d2 = softplus_f(dv.z) + 1.f, d3 = softplus_f(dv.w) + 1.f;
    float s0 = (c0 + 0 < 255) ? softplus_f(sv.x) : 0.f;
    float s1 = (c0 + 1 < 255) ? softplus_f(sv.y) : 0.f;
    float s2 = (c0 + 2 < 255) ? softplus_f(sv.z) : 0.f;
    float s3 = (c0 + 3 < 255) ? softplus_f(sv.w) : 0.f;
    invd[sub][c0 + 0] = 1.f / d0;  gs[sub][c0 + 0] = -s0 / d0;
    invd[sub][c0 + 1] = 1.f / d1;  gs[sub][c0 + 1] = -s1 / d1;
    invd[sub][c0 + 2] = 1.f / d2;  gs[sub][c0 + 2] = -s2 / d2;
    invd[sub][c0 + 3] = 1.f / d3;  gs[sub][c0 + 3] = -s3 / d3;
    __syncthreads();

    float p0 = 1.f, p1 = 1.f, p2 = 1.f, p3 = 1.f;
    float* op = out + MU_ELEMS + ((size_t)bz << 16) + c0;

#pragma unroll 4
    for (int r = 0; r < 256; ++r) {
        float iv = invd[sub][r];
        float gv = gs[sub][r];
        float4 v = make_float4(0.f, 0.f, 0.f, 0.f);
        if (r >= c0)     { v.x = p0 * iv; if (!isfinite(v.x)) v.x = 0.f; p0 *= gv; }
        if (r >= c0 + 1) { v.y = p1 * iv; if (!isfinite(v.y)) v.y = 0.f; p1 *= gv; }
        if (r >= c0 + 2) { v.z = p2 * iv; if (!isfinite(v.z)) v.z = 0.f; p2 *= gv; }
        if (r >= c0 + 3) { v.w = p3 * iv; if (!isfinite(v.w)) v.w = 0.f; p3 *= gv; }
        *(float4*)&op[(size_t)r << 8] = v;
    }
}

// ---------------------------------------------------------------------------
extern "C" void kernel_launch(void* const* d_in, const int* in_sizes, int n_in,
                              void* d_out, int out_size)
{
    const float* x  = (const float*)d_in[0];
    const float* W0 = (const float*)d_in[1];
    const float* b0 = (const float*)d_in[2];
    const float* W1 = (const float*)d_in[3];
    const float* b1 = (const float*)d_in[4];
    const float* W2 = (const float*)d_in[5];
    const float* b2 = (const float*)d_in[6];
    float* out = (float*)d_out;

    float *h0, *h1, *st, *wt0, *wt1, *wt2;
    cudaGetSymbolAddress((void**)&h0,  g_h0);
    cudaGetSymbolAddress((void**)&h1,  g_h1);
    cudaGetSymbolAddress((void**)&st,  g_stats);
    cudaGetSymbolAddress((void**)&wt0, g_wt0);
    cudaGetSymbolAddress((void**)&wt1, g_wt1);
    cudaGetSymbolAddress((void**)&wt2, g_wt2);

    // transpose all weights:   (192+768)*256 + 768*128 = 344064 elems
    transpose_w_kernel<<<1344, 256>>>(W0, W1, W2);

    // conv0: CIN=64  -> 256 ch, relu   (grid 8x4x32 = 1024 blocks)
    conv_kernel<C_IN, true><<<dim3(8, 4, BATCH), 128>>>(x,  wt0, b0, h0, HID0, 256);
    // conv1: CIN=256 -> 256 ch, relu   (grid 1024)
    conv_kernel<HID0, true><<<dim3(8, 4, BATCH), 128>>>(h0, wt1, b1, h1, HID1, 256);
    // conv2: CIN=256 -> 96 ch, linear  (o padded to 128 in Wt2, grid 512)
    conv_kernel<HID1, false><<<dim3(8, 2, BATCH), 128>>>(h1, wt2, b2, st, COUT2, 128);

    // mu -> first 262144 outputs
    mu_kernel<<<MU_ELEMS / 1024, 256>>>(st, out);
    // scale_tril -> remaining 67.1M outputs
    tri_kernel<<<(BATCH * ZDIM) / 4, 256>>>(st, out);
}

// round 9
// speedup vs baseline: 2.9260x; 1.0859x over previous
#include <cuda_runtime.h>
#include <cuda_bf16.h>
#include <cstdint>
#include <math.h>

// Problem constants
#define BATCH 32
#define C_IN  64
#define T_LEN 256
#define ZDIM  32
#define HID0  256
#define HID1  256
#define COUT2 96          // 3*Z
#define MU_ELEMS (BATCH*ZDIM*T_LEN)            // 262144

typedef unsigned long long u64;

// Scratch (no allocations allowed -> __device__ globals)
__device__ float g_h0[BATCH * HID0 * T_LEN];       // 8 MB
__device__ float g_h1[BATCH * HID1 * T_LEN];       // 8 MB
__device__ float g_stats[BATCH * COUT2 * T_LEN];   // 3 MB
__device__ float g_wt0[192 * 256];                 // W0 transposed [i*3+k][o]
__device__ float g_wt1[768 * 256];                 // W1 transposed
__device__ float g_wt2[768 * 96];                  // W2 transposed (exact, no pad)

// ---------------------------------------------------------------------------
// packed-f32x2 helpers (FFMA2: only reachable via PTX fma.rn.f32x2)
// ---------------------------------------------------------------------------
__device__ __forceinline__ u64 splat2(float x) {
    u64 r; asm("mov.b64 %0,{%1,%1};" : "=l"(r) : "f"(x)); return r;
}
__device__ __forceinline__ void fma2(u64& d, u64 a, u64 b) {
    asm("fma.rn.f32x2 %0,%1,%2,%0;" : "+l"(d) : "l"(a), "l"(b));
}
__device__ __forceinline__ float2 unpk(u64 v) {
    float2 f; asm("mov.b64 {%0,%1},%2;" : "=f"(f.x), "=f"(f.y) : "l"(v)); return f;
}

// ---------------------------------------------------------------------------
// cp.async helpers
// ---------------------------------------------------------------------------
__device__ __forceinline__ unsigned int s2u(const void* p) {
    unsigned int a;
    asm("{.reg .u64 t; cvta.to.shared.u64 t,%1; cvt.u32.u64 %0,t;}" : "=r"(a) : "l"(p));
    return a;
}
__device__ __forceinline__ void cp16(void* d, const void* s) {
    asm volatile("cp.async.ca.shared.global [%0],[%1],16;" :: "r"(s2u(d)), "l"(s));
}
__device__ __forceinline__ void cp4z(void* d, const void* s, bool v) {
    int sz = v ? 4 : 0;      // src-size 0 -> zero-fill, no read
    asm volatile("cp.async.ca.shared.global [%0],[%1],4,%2;" :: "r"(s2u(d)), "l"(s), "r"(sz));
}
#define CP_COMMIT() asm volatile("cp.async.commit_group;")

// ---------------------------------------------------------------------------
// Weight transpose pre-kernel: W[o][i][k] -> Wt[(i*3+k)][o]
// ---------------------------------------------------------------------------
__global__ __launch_bounds__(256)
void transpose_w_kernel(const float* __restrict__ W0, const float* __restrict__ W1,
                        const float* __restrict__ W2)
{
    int e = blockIdx.x * 256 + threadIdx.x;
    const int N0 = 192 * 256, N1 = 768 * 256, N2 = 768 * 96;
    if (e < N0) {
        int r = e >> 8, o = e & 255;
        int i = r / 3, k = r - 3 * i;
        g_wt0[e] = W0[(o * 64 + i) * 3 + k];
    } else if (e < N0 + N1) {
        int e1 = e - N0;
        int r = e1 >> 8, o = e1 & 255;
        int i = r / 3, k = r - 3 * i;
        g_wt1[e1] = W1[(o * 256 + i) * 3 + k];
    } else if (e < N0 + N1 + N2) {
        int e2 = e - N0 - N1;
        int r = e2 / 96, o = e2 - 96 * r;
        int i = r / 3, k = r - 3 * i;
        g_wt2[e2] = W2[(o * 256 + i) * 3 + k];
    }
}

// ---------------------------------------------------------------------------
// Conv1d (K=3, SAME) tiled GEMM, packed-f32x2 math, 3-stage cp.async pipeline.
// 128 threads.  Tile TILE_O x TILE_T, micro-tile 4o x 4t per thread.
// Xs layout per stage/row: cols [0,TILE_T) = t=bt+c, col TILE_T = x[bt+TILE_T],
// col TILE_T+1 = x[bt-1]  (main tile 16B-aligned for cp.async).
// ---------------------------------------------------------------------------
template<int CIN, bool RELU, int TILE_O, int TILE_T>
__global__ __launch_bounds__(128, 8)
void conv_kernel(const float* __restrict__ X, const float* __restrict__ Wt,
                 const float* __restrict__ Bias, float* __restrict__ Y,
                 int COUT, int WSTRIDE)
{
    constexpr int CI   = 8;            // ci rows per stage
    constexpr int NIT  = CIN / CI;     // 8 or 32  (>= 3)
    constexpr int XCOL = TILE_T + 4;   // keeps rows 16B-aligned
    constexpr int TTHR = TILE_T / 4;   // threads along t

    __shared__ __align__(16) float Xs[3][CI][XCOL];
    __shared__ __align__(16) float Ws[3][CI * 3][TILE_O];

    const int tid = threadIdx.x;
    const int tx  = tid % TTHR;
    const int ty  = tid / TTHR;
    const int bt  = blockIdx.x * TILE_T;
    const int bo  = blockIdx.y * TILE_O;
    const int b   = blockIdx.z;

    const float* Xb = X + (size_t)b * CIN * T_LEN;

    auto load_stage = [&](int ci0, int s) {
        const float* xb = Xb + (size_t)ci0 * T_LEN;
        // main X tile: CI rows x TILE_T cols, 16B chunks
        for (int idx = tid; idx < CI * TILE_T / 4; idx += 128) {
            int row = idx / (TILE_T / 4), c4 = idx % (TILE_T / 4);
            cp16(&Xs[s][row][4 * c4], xb + row * T_LEN + bt + 4 * c4);
        }
        // halos: side 0 -> col TILE_T (t=bt+TILE_T), side 1 -> col TILE_T+1 (t=bt-1)
        if (tid < CI * 2) {
            int row = tid >> 1, side = tid & 1;
            int t = side ? (bt - 1) : (bt + TILE_T);
            bool ok = (t >= 0) && (t < T_LEN);
            cp4z(&Xs[s][row][TILE_T + side], xb + row * T_LEN + (ok ? t : 0), ok);
        }
        // W tile: CI*3 rows x TILE_O cols
        for (int idx = tid; idx < CI * 3 * TILE_O / 4; idx += 128) {
            int row = idx / (TILE_O / 4), c4 = idx % (TILE_O / 4);
            cp16(&Ws[s][row][4 * c4],
                 Wt + (size_t)(3 * ci0 + row) * WSTRIDE + bo + 4 * c4);
        }
    };

    u64 acc[2][4];
#pragma unroll
    for (int p = 0; p < 2; ++p)
#pragma unroll
        for (int t = 0; t < 4; ++t) acc[p][t] = 0ull;

    load_stage(0,  0); CP_COMMIT();
    load_stage(CI, 1); CP_COMMIT();

#pragma unroll 1
    for (int it = 0; it < NIT; ++it) {
        if (it < NIT - 1) asm volatile("cp.async.wait_group 1;");
        else              asm volatile("cp.async.wait_group 0;");
        __syncthreads();                       // stage 'it' visible; compute(it-1) retired everywhere
        if (it + 2 < NIT) { load_stage((it + 2) * CI, (it + 2) % 3); CP_COMMIT(); }

        const int s = it % 3;
#pragma unroll
        for (int il = 0; il < CI; ++il) {
            float  xl = Xs[s][il][tx ? 4 * tx - 1 : TILE_T + 1];   // x[t0-1]
            float4 a0 = *(const float4*)&Xs[s][il][4 * tx];        // x[t0..t0+3]
            float  xr = Xs[s][il][4 * tx + 4];                     // x[t0+4] (last thread hits halo col)
            u64 xs[6];
            xs[0] = splat2(xl);   xs[1] = splat2(a0.x); xs[2] = splat2(a0.y);
            xs[3] = splat2(a0.z); xs[4] = splat2(a0.w); xs[5] = splat2(xr);
#pragma unroll
            for (int k = 0; k < 3; ++k) {
                ulonglong2 w = *(const ulonglong2*)&Ws[s][il * 3 + k][4 * ty];
#pragma unroll
                for (int tt = 0; tt < 4; ++tt) {
                    fma2(acc[0][tt], w.x, xs[tt + k]);
                    fma2(acc[1][tt], w.y, xs[tt + k]);
                }
            }
        }
    }

    // epilogue: unpack pairs, bias (+relu), 1x float4 store per o-row
#pragma unroll
    for (int p = 0; p < 2; ++p) {
        int o0 = bo + 4 * ty + 2 * p;
        float blo = Bias[o0];
        float bhi = Bias[o0 + 1];
        float lo[4], hi[4];
#pragma unroll
        for (int tt = 0; tt < 4; ++tt) {
            float2 f = unpk(acc[p][tt]);
            lo[tt] = f.x + blo;
            hi[tt] = f.y + bhi;
            if (RELU) { lo[tt] = fmaxf(lo[tt], 0.f); hi[tt] = fmaxf(hi[tt], 0.f); }
        }
        float* yp = Y + ((size_t)b * COUT + o0) * T_LEN + bt + 4 * tx;
        *(float4*)yp           = make_float4(lo[0], lo[1], lo[2], lo[3]);
        *(float4*)(yp + T_LEN) = make_float4(hi[0], hi[1], hi[2], hi[3]);
    }
}

__device__ __forceinline__ float softplus_f(float x)
{
    return fmaxf(x, 0.f) + log1pf(expf(-fabsf(x)));
}

// ---------------------------------------------------------------------------
// Triangular fill + fused mu copy.
// cov_u[c][r] = (1/d_r) * prod_{k=c}^{r-1} (-s_k/d_k); scale_tril[r][c]=cov_u[c][r].
// Thread = 4 consecutive columns (float4 STG). Block = 4 (b,z) pairs x 64 thr.
// Each sub-block also copies its mu row (64 lanes x 1 float4 = 256 floats).
// ---------------------------------------------------------------------------
__global__ __launch_bounds__(256)
void tri_kernel(const float* __restrict__ stats, float* __restrict__ out)
{
    __shared__ float invd[4][256];
    __shared__ float gs[4][256];

    const int tid  = threadIdx.x;
    const int sub  = tid >> 6;          // which bz within block
    const int lane = tid & 63;
    const int bz   = blockIdx.x * 4 + sub;
    const int b    = bz >> 5;
    const int z    = bz & 31;
    const int c0   = lane * 4;

    // fused mu copy: mu[b][z][:] -> out[bz*256 ..]
    {
        float4 mv = *(const float4*)(stats + ((size_t)b * COUT2 + z) * T_LEN + c0);
        *(float4*)(out + ((size_t)bz << 8) + c0) = mv;
    }

    const float* sd = stats + ((size_t)b * COUT2 + 32 + 2 * z) * T_LEN;
    const float* ss = sd + T_LEN;

    float4 dv = *(const float4*)(sd + c0);
    float4 sv = *(const float4*)(ss + c0);
    float d0 = softplus_f(dv.x) + 1.f, d1 = softplus_f(dv.y) + 1.f;
    float d2 = softplus_f(dv.z) + 1.f, d3 = softplus_f(dv.w) + 1.f;
    float s0 = (c0 + 0 < 255) ? softplus_f(sv.x) : 0.f;
    float s1 = (c0 + 1 < 255) ? softplus_f(sv.y) : 0.f;
    float s2 = (c0 + 2 < 255) ? softplus_f(sv.z) : 0.f;
    float s3 = (c0 + 3 < 255) ? softplus_f(sv.w) : 0.f;
    invd[sub][c0 + 0] = 1.f / d0;  gs[sub][c0 + 0] = -s0 / d0;
    invd[sub][c0 + 1] = 1.f / d1;  gs[sub][c0 + 1] = -s1 / d1;
    invd[sub][c0 + 2] = 1.f / d2;  gs[sub][c0 + 2] = -s2 / d2;
    invd[sub][c0 + 3] = 1.f / d3;  gs[sub][c0 + 3] = -s3 / d3;
    __syncthreads();

    float p0 = 1.f, p1 = 1.f, p2 = 1.f, p3 = 1.f;
    float* op = out + MU_ELEMS + ((size_t)bz << 16) + c0;

#pragma unroll 4
    for (int r = 0; r < 256; ++r) {
        float iv = invd[sub][r];
        float gv = gs[sub][r];
        float4 v = make_float4(0.f, 0.f, 0.f, 0.f);
        if (r >= c0)     { v.x = p0 * iv; if (!isfinite(v.x)) v.x = 0.f; p0 *= gv; }
        if (r >= c0 + 1) { v.y = p1 * iv; if (!isfinite(v.y)) v.y = 0.f; p1 *= gv; }
        if (r >= c0 + 2) { v.z = p2 * iv; if (!isfinite(v.z)) v.z = 0.f; p2 *= gv; }
        if (r >= c0 + 3) { v.w = p3 * iv; if (!isfinite(v.w)) v.w = 0.f; p3 *= gv; }
        *(float4*)&op[(size_t)r << 8] = v;
    }
}

// ---------------------------------------------------------------------------
extern "C" void kernel_launch(void* const* d_in, const int* in_sizes, int n_in,
                              void* d_out, int out_size)
{
    const float* x  = (const float*)d_in[0];
    const float* W0 = (const float*)d_in[1];
    const float* b0 = (const float*)d_in[2];
    const float* W1 = (const float*)d_in[3];
    const float* b1 = (const float*)d_in[4];
    const float* W2 = (const float*)d_in[5];
    const float* b2 = (const float*)d_in[6];
    float* out = (float*)d_out;

    float *h0, *h1, *st, *wt0, *wt1, *wt2;
    cudaGetSymbolAddress((void**)&h0,  g_h0);
    cudaGetSymbolAddress((void**)&h1,  g_h1);
    cudaGetSymbolAddress((void**)&st,  g_stats);
    cudaGetSymbolAddress((void**)&wt0, g_wt0);
    cudaGetSymbolAddress((void**)&wt1, g_wt1);
    cudaGetSymbolAddress((void**)&wt2, g_wt2);

    // transpose all weights: (192+768)*256 + 768*96 = 319488 elems
    transpose_w_kernel<<<1248, 256>>>(W0, W1, W2);

    // conv0: CIN=64  -> 256 ch, relu   (tile 64o x 32t, grid 8x4x32 = 1024)
    conv_kernel<C_IN, true, 64, 32><<<dim3(8, 4, BATCH), 128>>>(x,  wt0, b0, h0, HID0, 256);
    // conv1: CIN=256 -> 256 ch, relu   (grid 1024)
    conv_kernel<HID0, true, 64, 32><<<dim3(8, 4, BATCH), 128>>>(h0, wt1, b1, h1, HID1, 256);
    // conv2: CIN=256 -> 96 ch, linear  (tile 32o x 64t, exact 3 bo-tiles, grid 384)
    conv_kernel<HID1, false, 32, 64><<<dim3(4, 3, BATCH), 128>>>(h1, wt2, b2, st, COUT2, 96);

    // mu fused into tri_kernel; scale_tril -> remaining 67.1M outputs
    tri_kernel<<<(BATCH * ZDIM) / 4, 256>>>(st, out);
}